// round 8
// baseline (speedup 1.0000x reference)
#include <cuda_runtime.h>

// ---------------------------------------------------------------------------
// EResidualBlockBucket: x -> grouped3x3+ReLU -> per-pixel bucket-indexed
// dynamic 3x3 conv (+per-pixel bias) -> ReLU -> 1x1 conv -> +x -> ReLU
//
// R7 lesson: per-element 4B cp.async = L1 wavefront storm (L1 59%), and the
// emb stream (32MB, cold DRAM every launch) ran at 5% of HBM because each
// icc iteration staged-then-stalled. R8: software-pipelined staging with
// plain coalesced LDG held in REGISTERS: while computing icc from smem
// buffer cur, the icc+1 weight slice (9 scalar LDG/thread, warp-coalesced)
// and patch float4s are in flight; STS after compute; ONE barrier per icc.
// ~18KB DRAM continuously outstanding per CTA, 2 CTAs/SM.
// ---------------------------------------------------------------------------

#define HPW 66                 // padded image width/height
#define HPSZ (64 * HPW * HPW)  // h_pad elements: [y][x][ic], ic fastest

// Zero-initialized at module load; k_gconv overwrites the interior each call,
// the 1-px halo border is never written -> stays zero (SAME padding).
__device__ __align__(16) float g_hpad[HPSZ];     // padded h, pixel-major

typedef unsigned long long ull;

__device__ __forceinline__ void ffma2(ull& d, ull a, ull b) {
    asm("fma.rn.f32x2 %0, %1, %2, %0;" : "+l"(d) : "l"(a), "l"(b));
}
__device__ __forceinline__ ull pack2(float v) {
    ull r; asm("mov.b64 %0, {%1, %1};" : "=l"(r) : "f"(v)); return r;
}
__device__ __forceinline__ ull packf(float lo, float hi) {
    ull r; asm("mov.b64 %0, {%1, %2};" : "=l"(r) : "f"(lo), "f"(hi)); return r;
}
__device__ __forceinline__ float2 unpack2(ull v) {
    float2 r; asm("mov.b64 {%0, %1}, %2;" : "=f"(r.x), "=f"(r.y) : "l"(v));
    return r;
}

// dynamic smem layout (bytes), all 16B aligned
#define SM_WS0 0
#define SM_WS1 18432
#define SM_PS0 36864
#define SM_PS1 (36864 + 9504)
#define SM_PL  (36864 + 19008)           // plist: 4096 ushort
#define SM_TOT (SM_PL + 8192)            // 64064 B

// ---------------- K1: grouped 3x3 conv + bias + ReLU -> g_hpad -------------
__global__ void __launch_bounds__(256) k_gconv(const float* __restrict__ x,
                                               const float* __restrict__ w1,
                                               const float* __restrict__ b1) {
    __shared__ float xs[16][18][18];
    __shared__ float ws[16][144];
    __shared__ float bs[16];

    int bx = blockIdx.x;
    int g = bx >> 4;
    int tile = bx & 15;
    int y0 = (tile >> 2) * 16, x0 = (tile & 3) * 16;
    int tid = threadIdx.x;

    for (int i = tid; i < 16 * 18 * 18; i += 256) {
        int ic = i / 324;
        int rem = i - ic * 324;
        int r = rem / 18, c = rem - r * 18;
        int yy = y0 - 1 + r, xx = x0 - 1 + c;
        float v = 0.f;
        if (yy >= 0 && yy < 64 && xx >= 0 && xx < 64)
            v = x[(g * 16 + ic) * 4096 + yy * 64 + xx];
        xs[ic][r][c] = v;
    }
    for (int i = tid; i < 16 * 144; i += 256) {
        int oc = i / 144;
        ws[oc][i - oc * 144] = w1[(g * 16 + oc) * 144 + (i - oc * 144)];
    }
    if (tid < 16) bs[tid] = b1[g * 16 + tid];
    __syncthreads();

    int r = tid >> 4, c = tid & 15;
    float acc[16];
#pragma unroll
    for (int j = 0; j < 16; ++j) acc[j] = bs[j];

    for (int ic = 0; ic < 16; ++ic) {
        float p[9];
#pragma unroll
        for (int dy = 0; dy < 3; ++dy)
#pragma unroll
            for (int dx = 0; dx < 3; ++dx)
                p[dy * 3 + dx] = xs[ic][r + dy][c + dx];
#pragma unroll
        for (int j = 0; j < 16; ++j) {
#pragma unroll
            for (int k = 0; k < 9; ++k)
                acc[j] = fmaf(ws[j][ic * 9 + k], p[k], acc[j]);
        }
    }
    float* dst = g_hpad + (((y0 + r + 1) * HPW) + (x0 + c + 1)) * 64 + g * 16;
#pragma unroll
    for (int j = 0; j < 16; ++j) dst[j] = fmaxf(acc[j], 0.f);
}

// ---------------- K2: bucket-grouped dynamic conv + fused epilogue ---------
// grid 216 x 512 threads (16 warps, warp w -> ocs [4w,4w+4) as f32x2 pairs),
// lanes = pixel slots. Register-pipelined staging, 1 barrier per icc.
__global__ void __launch_bounds__(512, 2)
k_dyn(const int* __restrict__ buckets, const float* __restrict__ emb,
      const float* __restrict__ x, const float* __restrict__ w2,
      const float* __restrict__ b2, float* __restrict__ out) {
    extern __shared__ __align__(16) char sm[];
    float* wsb[2] = { (float*)(sm + SM_WS0), (float*)(sm + SM_WS1) };
    float* psb[2] = { (float*)(sm + SM_PS0), (float*)(sm + SM_PS1) };
    unsigned short* plist = (unsigned short*)(sm + SM_PL);
    __shared__ int s_count;

    int t = blockIdx.x;
    int tid = threadIdx.x;
    if (tid == 0) s_count = 0;
    __syncthreads();
    for (int i = tid; i < 4096; i += 512) {
        if (buckets[i] == t) {
            int p = atomicAdd(&s_count, 1);
            plist[p] = (unsigned short)i;
        }
    }
    __syncthreads();
    int n = s_count;
    if (n == 0) return;

    int lane = tid & 31;
    int wid = tid >> 5;               // 0..15
    int oc_base = wid * 4;
    const float* W = emb + (size_t)t * 36928;

    // ---- per-thread invariant staging indices ----
    // patch item A (all threads): t2 = tid; item B (tid<64): t2 = tid+512
    int qA = tid & 1;
    int rA = tid >> 1;                 // 0..255
    int slotA = rA / 9, posA = rA - slotA * 9;
    int dyA = posA / 3, dxA = posA - dyA * 3;
    int psA = (qA * 36 + posA) * 33 + slotA;        // +j*297 for ic j of 4
    int gpA = (dyA * HPW + dxA) * 64 + qA * 4;      // + (y*66+x)*64 + icc
    int rB = rA + 256;                               // 256..287 (tid<64)
    int slotB = rB / 9, posB = rB - slotB * 9;
    int dyB = posB / 3, dxB = posB - dyB * 3;
    int psB = (qA * 36 + posB) * 33 + slotB;
    int gpB = (dyB * HPW + dxB) * 64 + qA * 4;
    // weights: 9 items; item k: i2 = tid + 512k -> oc, cl via increments
    int w_oc0 = tid / 72;
    int w_cl0 = tid - w_oc0 * 72;

    // per-bucket bias (hoisted: reused by every chunk)
    ull bias0 = packf(__ldg(W + (oc_base + 0) * 577 + 576),
                      __ldg(W + (oc_base + 1) * 577 + 576));
    ull bias1 = packf(__ldg(W + (oc_base + 2) * 577 + 576),
                      __ldg(W + (oc_base + 3) * 577 + 576));
    float eb0 = __ldg(b2 + oc_base + 0), eb1 = __ldg(b2 + oc_base + 1);
    float eb2 = __ldg(b2 + oc_base + 2), eb3 = __ldg(b2 + oc_base + 3);

    for (int chunk = 0; chunk < n; chunk += 32) {
        int pi = chunk + lane;
        int mypix = plist[pi < n ? pi : n - 1];

        // chunk-dependent patch gmem bases
        int pjA = chunk + slotA;
        int pxA = plist[pjA < n ? pjA : n - 1];
        int gA = ((pxA >> 6) * HPW + (pxA & 63)) * 64 + gpA;
        int pjB = chunk + slotB;
        int pxB = plist[pjB < n ? pjB : n - 1];
        int gB = ((pxB >> 6) * HPW + (pxB & 63)) * 64 + gpB;

        ull acc2[2] = { bias0, bias1 };

        // ---- staging helpers (register-held) ----
        float wreg[9];
        float4 pA, pB;
        auto load_w = [&](int icc8) {        // issue 9 coalesced LDGs
            const float* Wi = W + icc8 * 72;
            int oc = w_oc0, cl = w_cl0;
#pragma unroll
            for (int k = 0; k < 9; ++k) {
                wreg[k] = __ldg(Wi + oc * 577 + cl);
                oc += 7; cl += 8;
                if (cl >= 72) { cl -= 72; ++oc; }
            }
        };
        auto store_w = [&](float* dstb) {    // scatter STS pair-interleaved
            int oc = w_oc0, cl = w_cl0;
#pragma unroll
            for (int k = 0; k < 9; ++k) {
                dstb[(oc >> 1) * 144 + cl * 2 + (oc & 1)] = wreg[k];
                oc += 7; cl += 8;
                if (cl >= 72) { cl -= 72; ++oc; }
            }
        };
        auto load_p = [&](int icc8) {
            int icc = icc8 * 8;
            pA = *(const float4*)(g_hpad + gA + icc);
            if (tid < 64) pB = *(const float4*)(g_hpad + gB + icc);
        };
        auto store_p = [&](float* ps) {
            ps[psA + 0]   = pA.x;
            ps[psA + 297] = pA.y;
            ps[psA + 594] = pA.z;
            ps[psA + 891] = pA.w;
            if (tid < 64) {
                ps[psB + 0]   = pB.x;
                ps[psB + 297] = pB.y;
                ps[psB + 594] = pB.z;
                ps[psB + 891] = pB.w;
            }
        };

        // ---- prologue: stage icc 0 into buffer 0 ----
        load_w(0); load_p(0);
        store_w(wsb[0]); store_p(psb[0]);
        __syncthreads();

        for (int icc8 = 0; icc8 < 8; ++icc8) {
            int cur = icc8 & 1, nx = cur ^ 1;
            // issue next-slice loads BEFORE compute: latency hides under it
            if (icc8 < 7) { load_w(icc8 + 1); load_p(icc8 + 1); }

            // ---- compute from [cur]: 72 c x 2 oc-pairs per warp, FFMA2
            const float* psl = psb[cur] + lane;
            const ulonglong2* wp0 =
                ((const ulonglong2*)wsb[cur]) + (2 * wid) * 36;
            const ulonglong2* wp1 = wp0 + 36;
#pragma unroll
            for (int c4 = 0; c4 < 72; c4 += 4) {
                ull p0 = pack2(psl[(c4 + 0) * 33]);
                ull p1 = pack2(psl[(c4 + 1) * 33]);
                ull p2 = pack2(psl[(c4 + 2) * 33]);
                ull p3 = pack2(psl[(c4 + 3) * 33]);
                ulonglong2 a01 = wp0[(c4 >> 1)];
                ulonglong2 a23 = wp0[(c4 >> 1) + 1];
                ulonglong2 b01 = wp1[(c4 >> 1)];
                ulonglong2 b23 = wp1[(c4 >> 1) + 1];
                ffma2(acc2[0], a01.x, p0);
                ffma2(acc2[0], a01.y, p1);
                ffma2(acc2[0], a23.x, p2);
                ffma2(acc2[0], a23.y, p3);
                ffma2(acc2[1], b01.x, p0);
                ffma2(acc2[1], b01.y, p1);
                ffma2(acc2[1], b23.x, p2);
                ffma2(acc2[1], b23.y, p3);
            }
            if (icc8 < 7) { store_w(wsb[nx]); store_p(psb[nx]); }
            __syncthreads();   // BAR drains STS; next iter reads [nx]
        }

        // ---- fused epilogue: ReLU -> 1x1 conv (w2) + b2 -> +x -> ReLU
        float* ds = psb[0];   // ps/ws dead after final barrier
        float2 r01 = unpack2(acc2[0]);
        float2 r23 = unpack2(acc2[1]);
        ds[(oc_base + 0) * 33 + lane] = fmaxf(r01.x, 0.f);
        ds[(oc_base + 1) * 33 + lane] = fmaxf(r01.y, 0.f);
        ds[(oc_base + 2) * 33 + lane] = fmaxf(r23.x, 0.f);
        ds[(oc_base + 3) * 33 + lane] = fmaxf(r23.y, 0.f);
        __syncthreads();

        float eacc[4] = { eb0, eb1, eb2, eb3 };
#pragma unroll
        for (int blk = 0; blk < 4; ++blk) {
            float pv[16];
#pragma unroll
            for (int q = 0; q < 16; ++q)
                pv[q] = ds[(blk * 16 + q) * 33 + lane];
#pragma unroll
            for (int j = 0; j < 4; ++j) {
                const float4* wr = (const float4*)(w2 +
                    (oc_base + j) * 64 + blk * 16);
#pragma unroll
                for (int q4 = 0; q4 < 4; ++q4) {
                    float4 w = __ldg(wr + q4);
                    eacc[j] = fmaf(w.x, pv[q4 * 4 + 0], eacc[j]);
                    eacc[j] = fmaf(w.y, pv[q4 * 4 + 1], eacc[j]);
                    eacc[j] = fmaf(w.z, pv[q4 * 4 + 2], eacc[j]);
                    eacc[j] = fmaf(w.w, pv[q4 * 4 + 3], eacc[j]);
                }
            }
        }

        if (pi < n) {
#pragma unroll
            for (int j = 0; j < 4; ++j) {
                int o = oc_base + j;
                out[o * 4096 + mypix] =
                    fmaxf(eacc[j] + __ldg(x + o * 4096 + mypix), 0.f);
            }
        }
        __syncthreads();   // ds (= ps0) must drain before next chunk stages
    }
}

// ---------------------------------------------------------------------------
extern "C" void kernel_launch(void* const* d_in, const int* in_sizes, int n_in,
                              void* d_out, int out_size) {
    const float* x       = (const float*)d_in[0];
    const int*   buckets = (const int*)  d_in[1];
    const float* w1      = (const float*)d_in[2];
    const float* b1      = (const float*)d_in[3];
    const float* emb     = (const float*)d_in[4];
    const float* w2      = (const float*)d_in[5];
    const float* b2      = (const float*)d_in[6];
    float* out = (float*)d_out;

    cudaFuncSetAttribute(k_dyn, cudaFuncAttributeMaxDynamicSharedMemorySize,
                         SM_TOT);

    k_gconv<<<64, 256>>>(x, w1, b1);
    k_dyn<<<216, 512, SM_TOT>>>(buckets, emb, x, w2, b2, out);
}

// round 9
// speedup vs baseline: 1.0261x; 1.0261x over previous
#include <cuda_runtime.h>

// ---------------------------------------------------------------------------
// EResidualBlockBucket: x -> grouped3x3+ReLU -> per-pixel bucket-indexed
// dynamic 3x3 conv (+per-pixel bias) -> ReLU -> 1x1 conv -> +x -> ReLU
//
// R8 lesson: k_dyn is L1-work bound. R9 inner loop: weights c-linear in smem
// (uniform LDS.128), patches transposed ps[slot][76] (conflict-free LDS.128
// per lane), c-pair FFMA2 straight off ulonglong2 register pairs (no packing
// movs; even/odd horizontal add deferred to the end). 5 LDS.128 + 8 FFMA2
// per 512 MACs. Simple R6-style stage/compute with double buffers.
// ---------------------------------------------------------------------------

#define HPW 66                 // padded image width/height
#define HPSZ (64 * HPW * HPW)  // h_pad elements: [y][x][ic], ic fastest

// Zero-initialized at module load; k_gconv overwrites the interior each call,
// the 1-px halo border is never written -> stays zero (SAME padding).
__device__ __align__(16) float g_hpad[HPSZ];     // padded h, pixel-major

typedef unsigned long long ull;

__device__ __forceinline__ void ffma2(ull& d, ull a, ull b) {
    asm("fma.rn.f32x2 %0, %1, %2, %0;" : "+l"(d) : "l"(a), "l"(b));
}
__device__ __forceinline__ ull packf(float lo, float hi) {
    ull r; asm("mov.b64 %0, {%1, %2};" : "=l"(r) : "f"(lo), "f"(hi)); return r;
}
__device__ __forceinline__ float2 unpack2(ull v) {
    float2 r; asm("mov.b64 {%0, %1}, %2;" : "=f"(r.x), "=f"(r.y) : "l"(v));
    return r;
}

// dynamic smem layout (bytes); ws rows 76 floats = 304B (16B-aligned quads)
#define SM_WS0 0                         // 64*76*4 = 19456
#define SM_WS1 19456
#define SM_PS0 38912                     // 32*76*4 = 9728
#define SM_PS1 48640
#define SM_PL  58368                     // plist: 4096 ushort
#define SM_TOT (58368 + 8192)            // 66560 B

// ---------------- K1: grouped 3x3 conv + bias + ReLU -> g_hpad -------------
__global__ void __launch_bounds__(256) k_gconv(const float* __restrict__ x,
                                               const float* __restrict__ w1,
                                               const float* __restrict__ b1) {
    __shared__ float xs[16][18][18];
    __shared__ float ws[16][144];
    __shared__ float bs[16];

    int bx = blockIdx.x;
    int g = bx >> 4;
    int tile = bx & 15;
    int y0 = (tile >> 2) * 16, x0 = (tile & 3) * 16;
    int tid = threadIdx.x;

    for (int i = tid; i < 16 * 18 * 18; i += 256) {
        int ic = i / 324;
        int rem = i - ic * 324;
        int r = rem / 18, c = rem - r * 18;
        int yy = y0 - 1 + r, xx = x0 - 1 + c;
        float v = 0.f;
        if (yy >= 0 && yy < 64 && xx >= 0 && xx < 64)
            v = x[(g * 16 + ic) * 4096 + yy * 64 + xx];
        xs[ic][r][c] = v;
    }
    for (int i = tid; i < 16 * 144; i += 256) {
        int oc = i / 144;
        ws[oc][i - oc * 144] = w1[(g * 16 + oc) * 144 + (i - oc * 144)];
    }
    if (tid < 16) bs[tid] = b1[g * 16 + tid];
    __syncthreads();

    int r = tid >> 4, c = tid & 15;
    float acc[16];
#pragma unroll
    for (int j = 0; j < 16; ++j) acc[j] = bs[j];

    for (int ic = 0; ic < 16; ++ic) {
        float p[9];
#pragma unroll
        for (int dy = 0; dy < 3; ++dy)
#pragma unroll
            for (int dx = 0; dx < 3; ++dx)
                p[dy * 3 + dx] = xs[ic][r + dy][c + dx];
#pragma unroll
        for (int j = 0; j < 16; ++j) {
#pragma unroll
            for (int k = 0; k < 9; ++k)
                acc[j] = fmaf(ws[j][ic * 9 + k], p[k], acc[j]);
        }
    }
    float* dst = g_hpad + (((y0 + r + 1) * HPW) + (x0 + c + 1)) * 64 + g * 16;
#pragma unroll
    for (int j = 0; j < 16; ++j) dst[j] = fmaxf(acc[j], 0.f);
}

// ---------------- K2: bucket-grouped dynamic conv + fused epilogue ---------
// grid 216 x 512 threads (16 warps; warp w owns ocs [4w,4w+4)); lanes =
// pixel slots. Per icc: stage next buffer, compute current, one barrier.
__global__ void __launch_bounds__(512, 2)
k_dyn(const int* __restrict__ buckets, const float* __restrict__ emb,
      const float* __restrict__ x, const float* __restrict__ w2,
      const float* __restrict__ b2, float* __restrict__ out) {
    extern __shared__ __align__(16) char sm[];
    float* wsb[2] = { (float*)(sm + SM_WS0), (float*)(sm + SM_WS1) };
    float* psb[2] = { (float*)(sm + SM_PS0), (float*)(sm + SM_PS1) };
    unsigned short* plist = (unsigned short*)(sm + SM_PL);
    __shared__ int s_count;

    int t = blockIdx.x;
    int tid = threadIdx.x;
    if (tid == 0) s_count = 0;
    __syncthreads();
    for (int i = tid; i < 4096; i += 512) {
        if (buckets[i] == t) {
            int p = atomicAdd(&s_count, 1);
            plist[p] = (unsigned short)i;
        }
    }
    __syncthreads();
    int n = s_count;
    if (n == 0) return;

    int lane = tid & 31;
    int wid = tid >> 5;               // 0..15
    int oc_base = wid * 4;
    const float* W = emb + (size_t)t * 36928;

    // ---- per-thread invariant staging indices ----
    // patches: item A (all threads) = tid, item B (tid<64) = tid+512;
    // item -> (q = item&1, r = item>>1, slot = r/9, pos = r%9)
    int qA = tid & 1;
    int rA = tid >> 1;
    int slotA = rA / 9, posA = rA - slotA * 9;
    int dyA = posA / 3, dxA = posA - dyA * 3;
    int psA = slotA * 76 + qA * 36 + posA;          // writes at +0,+9,+18,+27
    int gpA = (dyA * HPW + dxA) * 64 + qA * 4;      // + (y*66+x)*64 + icc*8
    int rB = rA + 256;
    int slotB = rB / 9, posB = rB - slotB * 9;
    int dyB = posB / 3, dxB = posB - dyB * 3;
    int psB = slotB * 76 + qA * 36 + posB;
    int gpB = (dyB * HPW + dxB) * 64 + qA * 4;
    // weights: 9 items; i2 = tid + 512k -> oc = i2/72, cl = i2%72
    int w_oc0 = tid / 72;
    int w_cl0 = tid - w_oc0 * 72;

    // hoisted per-bucket constants
    ull bias2[4];
#pragma unroll
    for (int j = 0; j < 4; ++j)
        bias2[j] = packf(__ldg(W + (oc_base + j) * 577 + 576), 0.f);
    float eb[4];
#pragma unroll
    for (int j = 0; j < 4; ++j) eb[j] = __ldg(b2 + oc_base + j);

    // ---- staging helpers ----
    auto stage_w = [&](int icc8, float* dst) {
        const float* Wi = W + icc8 * 72;
        float v[9];
        int oc = w_oc0, cl = w_cl0;
#pragma unroll
        for (int k = 0; k < 9; ++k) {           // batch loads first
            v[k] = __ldg(Wi + oc * 577 + cl);
            oc += 7; cl += 8; if (cl >= 72) { cl -= 72; ++oc; }
        }
        oc = w_oc0; cl = w_cl0;
#pragma unroll
        for (int k = 0; k < 9; ++k) {           // then stores (c-linear)
            dst[oc * 76 + cl] = v[k];
            oc += 7; cl += 8; if (cl >= 72) { cl -= 72; ++oc; }
        }
    };

    for (int chunk = 0; chunk < n; chunk += 32) {
        int pi = chunk + lane;
        int mypix = plist[pi < n ? pi : n - 1];

        // chunk-dependent patch gmem bases
        int pjA = chunk + slotA;
        int pxA = plist[pjA < n ? pjA : n - 1];
        int gA = ((pxA >> 6) * HPW + (pxA & 63)) * 64 + gpA;
        int pjB = chunk + slotB;
        int pxB = plist[pjB < n ? pjB : n - 1];
        int gB = ((pxB >> 6) * HPW + (pxB & 63)) * 64 + gpB;

        auto stage_p = [&](int icc8, float* ps) {
            int icc = icc8 * 8;
            float4 vA = *(const float4*)(g_hpad + gA + icc);
            float4 vB;
            if (tid < 64) vB = *(const float4*)(g_hpad + gB + icc);
            ps[psA + 0]  = vA.x;
            ps[psA + 9]  = vA.y;
            ps[psA + 18] = vA.z;
            ps[psA + 27] = vA.w;
            if (tid < 64) {
                ps[psB + 0]  = vB.x;
                ps[psB + 9]  = vB.y;
                ps[psB + 18] = vB.z;
                ps[psB + 27] = vB.w;
            }
        };

        ull acc2[4] = { bias2[0], bias2[1], bias2[2], bias2[3] };

        stage_w(0, wsb[0]);
        stage_p(0, psb[0]);
        __syncthreads();

        for (int icc8 = 0; icc8 < 8; ++icc8) {
            int cur = icc8 & 1, nx = cur ^ 1;
            if (icc8 < 7) {                       // stage next buffer
                stage_w(icc8 + 1, wsb[nx]);
                stage_p(icc8 + 1, psb[nx]);
            }
            // ---- compute [cur]: per c-quad 5 LDS.128 + 8 FFMA2 ----
            const ulonglong2* Pp =
                (const ulonglong2*)(psb[cur] + lane * 76);
            const ulonglong2* W0 =
                (const ulonglong2*)(wsb[cur] + (oc_base + 0) * 76);
            const ulonglong2* W1 =
                (const ulonglong2*)(wsb[cur] + (oc_base + 1) * 76);
            const ulonglong2* W2 =
                (const ulonglong2*)(wsb[cur] + (oc_base + 2) * 76);
            const ulonglong2* W3 =
                (const ulonglong2*)(wsb[cur] + (oc_base + 3) * 76);
#pragma unroll
            for (int c8 = 0; c8 < 18; ++c8) {
                ulonglong2 P = Pp[c8];
                ulonglong2 a0 = W0[c8];
                ffma2(acc2[0], a0.x, P.x); ffma2(acc2[0], a0.y, P.y);
                ulonglong2 a1 = W1[c8];
                ffma2(acc2[1], a1.x, P.x); ffma2(acc2[1], a1.y, P.y);
                ulonglong2 a2 = W2[c8];
                ffma2(acc2[2], a2.x, P.x); ffma2(acc2[2], a2.y, P.y);
                ulonglong2 a3 = W3[c8];
                ffma2(acc2[3], a3.x, P.x); ffma2(acc2[3], a3.y, P.y);
            }
            __syncthreads();
        }

        // ---- fused epilogue: ReLU -> 1x1 conv (w2) + b2 -> +x -> ReLU
        float* ds = psb[0];   // ps/ws dead after final barrier (64*33 fits)
#pragma unroll
        for (int j = 0; j < 4; ++j) {
            float2 e = unpack2(acc2[j]);
            ds[(oc_base + j) * 33 + lane] = fmaxf(e.x + e.y, 0.f);
        }
        __syncthreads();

        float eacc[4] = { eb[0], eb[1], eb[2], eb[3] };
#pragma unroll
        for (int blk = 0; blk < 4; ++blk) {
            float pv[16];
#pragma unroll
            for (int q = 0; q < 16; ++q)
                pv[q] = ds[(blk * 16 + q) * 33 + lane];
#pragma unroll
            for (int j = 0; j < 4; ++j) {
                const float4* wr = (const float4*)(w2 +
                    (oc_base + j) * 64 + blk * 16);
#pragma unroll
                for (int q4 = 0; q4 < 4; ++q4) {
                    float4 w = __ldg(wr + q4);
                    eacc[j] = fmaf(w.x, pv[q4 * 4 + 0], eacc[j]);
                    eacc[j] = fmaf(w.y, pv[q4 * 4 + 1], eacc[j]);
                    eacc[j] = fmaf(w.z, pv[q4 * 4 + 2], eacc[j]);
                    eacc[j] = fmaf(w.w, pv[q4 * 4 + 3], eacc[j]);
                }
            }
        }

        if (pi < n) {
#pragma unroll
            for (int j = 0; j < 4; ++j) {
                int o = oc_base + j;
                out[o * 4096 + mypix] =
                    fmaxf(eacc[j] + __ldg(x + o * 4096 + mypix), 0.f);
            }
        }
        __syncthreads();   // ds (= ps0) must drain before next chunk stages
    }
}

// ---------------------------------------------------------------------------
extern "C" void kernel_launch(void* const* d_in, const int* in_sizes, int n_in,
                              void* d_out, int out_size) {
    const float* x       = (const float*)d_in[0];
    const int*   buckets = (const int*)  d_in[1];
    const float* w1      = (const float*)d_in[2];
    const float* b1      = (const float*)d_in[3];
    const float* emb     = (const float*)d_in[4];
    const float* w2      = (const float*)d_in[5];
    const float* b2      = (const float*)d_in[6];
    float* out = (float*)d_out;

    cudaFuncSetAttribute(k_dyn, cudaFuncAttributeMaxDynamicSharedMemorySize,
                         SM_TOT);

    k_gconv<<<64, 256>>>(x, w1, b1);
    k_dyn<<<216, 512, SM_TOT>>>(buckets, emb, x, w2, b2, out);
}

// round 10
// speedup vs baseline: 1.2437x; 1.2120x over previous
#include <cuda_runtime.h>

// ---------------------------------------------------------------------------
// EResidualBlockBucket: x -> grouped3x3+ReLU -> per-pixel bucket-indexed
// dynamic 3x3 conv (+per-pixel bias) -> ReLU -> 1x1 conv -> +x -> ReLU
//
// R9 diagnosis: each CTA runs ~1 chunk; R6's weight staging serialized 9
// LDG->STS DRAM round trips per icc (rolled loop), and R8/R9's batched fix
// spilled because __launch_bounds__(512,2) capped regs at 64. R10: 256-thr
// CTAs (8 warps x 8 ocs), batched 18-LDG weight staging held in registers
// with NO register cap (no min-blocks) -> one DRAM latency per icc, no
// spills. R6's proven compute loop and single-buffer barriers kept.
// ---------------------------------------------------------------------------

#define HPW 66                 // padded image width/height
#define HPSZ (64 * HPW * HPW)  // h_pad elements: [y][x][ic], ic fastest

// Zero-initialized at module load; k_gconv overwrites the interior each call,
// the 1-px halo border is never written -> stays zero (SAME padding).
__device__ __align__(16) float g_hpad[HPSZ];     // padded h, pixel-major

typedef unsigned long long ull;

__device__ __forceinline__ void ffma2(ull& d, ull a, ull b) {
    asm("fma.rn.f32x2 %0, %1, %2, %0;" : "+l"(d) : "l"(a), "l"(b));
}
__device__ __forceinline__ ull pack2(float v) {
    ull r; asm("mov.b64 %0, {%1, %1};" : "=l"(r) : "f"(v)); return r;
}
__device__ __forceinline__ ull packf(float lo, float hi) {
    ull r; asm("mov.b64 %0, {%1, %2};" : "=l"(r) : "f"(lo), "f"(hi)); return r;
}
__device__ __forceinline__ float2 unpack2(ull v) {
    float2 r; asm("mov.b64 {%0, %1}, %2;" : "=f"(r.x), "=f"(r.y) : "l"(v));
    return r;
}

// ---------------- K1: grouped 3x3 conv + bias + ReLU -> g_hpad -------------
__global__ void __launch_bounds__(256) k_gconv(const float* __restrict__ x,
                                               const float* __restrict__ w1,
                                               const float* __restrict__ b1) {
    __shared__ float xs[16][18][18];
    __shared__ float ws[16][144];
    __shared__ float bs[16];

    int bx = blockIdx.x;
    int g = bx >> 4;
    int tile = bx & 15;
    int y0 = (tile >> 2) * 16, x0 = (tile & 3) * 16;
    int tid = threadIdx.x;

    for (int i = tid; i < 16 * 18 * 18; i += 256) {
        int ic = i / 324;
        int rem = i - ic * 324;
        int r = rem / 18, c = rem - r * 18;
        int yy = y0 - 1 + r, xx = x0 - 1 + c;
        float v = 0.f;
        if (yy >= 0 && yy < 64 && xx >= 0 && xx < 64)
            v = x[(g * 16 + ic) * 4096 + yy * 64 + xx];
        xs[ic][r][c] = v;
    }
    for (int i = tid; i < 16 * 144; i += 256) {
        int oc = i / 144;
        ws[oc][i - oc * 144] = w1[(g * 16 + oc) * 144 + (i - oc * 144)];
    }
    if (tid < 16) bs[tid] = b1[g * 16 + tid];
    __syncthreads();

    int r = tid >> 4, c = tid & 15;
    float acc[16];
#pragma unroll
    for (int j = 0; j < 16; ++j) acc[j] = bs[j];

    for (int ic = 0; ic < 16; ++ic) {
        float p[9];
#pragma unroll
        for (int dy = 0; dy < 3; ++dy)
#pragma unroll
            for (int dx = 0; dx < 3; ++dx)
                p[dy * 3 + dx] = xs[ic][r + dy][c + dx];
#pragma unroll
        for (int j = 0; j < 16; ++j) {
#pragma unroll
            for (int k = 0; k < 9; ++k)
                acc[j] = fmaf(ws[j][ic * 9 + k], p[k], acc[j]);
        }
    }
    float* dst = g_hpad + (((y0 + r + 1) * HPW) + (x0 + c + 1)) * 64 + g * 16;
#pragma unroll
    for (int j = 0; j < 16; ++j) dst[j] = fmaxf(acc[j], 0.f);
}

// ---------------- K2: bucket-grouped dynamic conv + fused epilogue ---------
// grid 216 x 256 threads (8 warps; warp w -> ocs [8w,8w+8) as 4 f32x2
// pairs); lanes = pixel slots. Single-buffered icc staging (R6 style) with
// BATCHED register-held loads (one DRAM latency per icc), no register cap.
__global__ void __launch_bounds__(256)
k_dyn(const int* __restrict__ buckets, const float* __restrict__ emb,
      const float* __restrict__ x, const float* __restrict__ w2,
      const float* __restrict__ b2, float* __restrict__ out) {
    // ws: pair-interleaved ws[pair*144 + c*2 + parity] -> LDS.128 gives
    // f32x2 operands for 2 consecutive c for one oc-pair.
    __shared__ __align__(16) float ws[64 * 72];   // 18432 B
    __shared__ __align__(16) float ps[72 * 33];   // patches [c][slot], 9504 B
    __shared__ unsigned short plist[4096];
    __shared__ int s_count;
    float* ds = ps;   // epilogue overlay (64*33 = 2112 <= 2376 floats)

    int t = blockIdx.x;
    int tid = threadIdx.x;
    if (tid == 0) s_count = 0;
    __syncthreads();
    for (int i = tid; i < 4096; i += 256) {
        if (buckets[i] == t) {
            int p = atomicAdd(&s_count, 1);
            plist[p] = (unsigned short)i;
        }
    }
    __syncthreads();
    int n = s_count;
    if (n == 0) return;

    int lane = tid & 31;
    int wid = tid >> 5;               // 0..7
    int oc_base = wid * 8;
    const float* W = emb + (size_t)t * 36928;

    // ---- per-thread invariant staging indices ----
    // patches: items A (tid), B (tid+256), C (tid+512, tid<64)
    int qA = tid & 1;
    int rA = tid >> 1;                               // 0..127
    int slotA = rA / 9, posA = rA - slotA * 9;
    int dyA = posA / 3, dxA = posA - dyA * 3;
    int psA = qA * 1188 + posA * 33 + slotA;         // +j*297, j=0..3
    int gpA = (dyA * HPW + dxA) * 64 + qA * 4;
    int rB = rA + 128;                               // 128..255
    int slotB = rB / 9, posB = rB - slotB * 9;
    int dyB = posB / 3, dxB = posB - dyB * 3;
    int psB = qA * 1188 + posB * 33 + slotB;
    int gpB = (dyB * HPW + dxB) * 64 + qA * 4;
    int rC = rA + 256;                               // 256..287 (tid<64)
    int slotC = rC / 9, posC = rC - slotC * 9;
    int dyC = posC / 3, dxC = posC - dyC * 3;
    int psC = qA * 1188 + posC * 33 + slotC;
    int gpC = (dyC * HPW + dxC) * 64 + qA * 4;
    // weights: 18 items, i2 = tid + 256k; oc=i2/72, cl=i2%72 incremental
    int w_oc0 = tid / 72;
    int w_cl0 = tid - w_oc0 * 72;
    int w_go0 = w_oc0 * 577 + w_cl0;

    // hoisted per-bucket constants
    ull bias2[4];
#pragma unroll
    for (int j = 0; j < 4; ++j)
        bias2[j] = packf(__ldg(W + (oc_base + 2 * j) * 577 + 576),
                         __ldg(W + (oc_base + 2 * j + 1) * 577 + 576));
    float eb[8];
#pragma unroll
    for (int j = 0; j < 8; ++j) eb[j] = __ldg(b2 + oc_base + j);

    for (int chunk = 0; chunk < n; chunk += 32) {
        int pi = chunk + lane;
        int mypix = plist[pi < n ? pi : n - 1];

        // chunk-dependent patch gmem bases
        int pjA = chunk + slotA;
        int pxA = plist[pjA < n ? pjA : n - 1];
        int gA = ((pxA >> 6) * HPW + (pxA & 63)) * 64 + gpA;
        int pjB = chunk + slotB;
        int pxB = plist[pjB < n ? pjB : n - 1];
        int gB = ((pxB >> 6) * HPW + (pxB & 63)) * 64 + gpB;
        int pjC = chunk + slotC;
        int pxC = plist[pjC < n ? pjC : n - 1];
        int gC = ((pxC >> 6) * HPW + (pxC & 63)) * 64 + gpC;

        ull acc2[4] = { bias2[0], bias2[1], bias2[2], bias2[3] };

        for (int icc8 = 0; icc8 < 8; ++icc8) {
            int icc = icc8 * 8;

            // ---- stage: ALL loads issued first (one DRAM latency) ----
            float wv[18];
            {
                const float* Wi = W + icc8 * 72;
                int go = w_go0;
#pragma unroll
                for (int k = 0; k < 18; ++k) {
                    wv[k] = __ldg(Wi + go);
                    // i2 += 256: oc += 3, cl += 40 (wrap: ++oc, cl -= 72)
                    int cl_t = w_cl0;  // recompute cl path below via go only
                    (void)cl_t;
                    go += 1771;
                    // wrap detection via running cl
                }
            }
            // recompute go path with explicit oc/cl for stores AND fix the
            // wrap in loads: redo loads with correct wrap (see below).
            // NOTE: the load loop above must match store indices; do both
            // with one canonical walk:
            {
                // canonical walk (loads already issued? -> No: to keep
                // correctness, the real implementation below re-issues with
                // wrap; ptxas dedups identical loads).
            }
            {
                const float* Wi = W + icc8 * 72;
                int oc = w_oc0, cl = w_cl0, go = w_go0;
#pragma unroll
                for (int k = 0; k < 18; ++k) {
                    wv[k] = __ldg(Wi + go);
                    oc += 3; cl += 40; go += 1771;
                    if (cl >= 72) { cl -= 72; ++oc; go += 505; }
                }
            }
            float4 vA = *(const float4*)(g_hpad + gA + icc);
            float4 vB = *(const float4*)(g_hpad + gB + icc);
            float4 vC;
            if (tid < 64) vC = *(const float4*)(g_hpad + gC + icc);

            // ---- then all stores ----
            {
                int oc = w_oc0, cl = w_cl0;
#pragma unroll
                for (int k = 0; k < 18; ++k) {
                    ws[(oc >> 1) * 144 + cl * 2 + (oc & 1)] = wv[k];
                    oc += 3; cl += 40;
                    if (cl >= 72) { cl -= 72; ++oc; }
                }
            }
            ps[psA + 0]   = vA.x;
            ps[psA + 297] = vA.y;
            ps[psA + 594] = vA.z;
            ps[psA + 891] = vA.w;
            ps[psB + 0]   = vB.x;
            ps[psB + 297] = vB.y;
            ps[psB + 594] = vB.z;
            ps[psB + 891] = vB.w;
            if (tid < 64) {
                ps[psC + 0]   = vC.x;
                ps[psC + 297] = vC.y;
                ps[psC + 594] = vC.z;
                ps[psC + 891] = vC.w;
            }
            __syncthreads();

            // ---- compute: 72 c x 4 oc-pairs per warp, FFMA2 ----
            const float* psl = ps + lane;
            const ulonglong2* w0 = (const ulonglong2*)(ws + (4 * wid + 0) * 144);
            const ulonglong2* w1 = (const ulonglong2*)(ws + (4 * wid + 1) * 144);
            const ulonglong2* w2p = (const ulonglong2*)(ws + (4 * wid + 2) * 144);
            const ulonglong2* w3 = (const ulonglong2*)(ws + (4 * wid + 3) * 144);
#pragma unroll 6
            for (int c4 = 0; c4 < 72; c4 += 4) {
                ull p0 = pack2(psl[(c4 + 0) * 33]);
                ull p1 = pack2(psl[(c4 + 1) * 33]);
                ull p2 = pack2(psl[(c4 + 2) * 33]);
                ull p3 = pack2(psl[(c4 + 3) * 33]);
                int q = c4 >> 1;
                ulonglong2 a = w0[q], b = w0[q + 1];
                ffma2(acc2[0], a.x, p0); ffma2(acc2[0], a.y, p1);
                ffma2(acc2[0], b.x, p2); ffma2(acc2[0], b.y, p3);
                a = w1[q]; b = w1[q + 1];
                ffma2(acc2[1], a.x, p0); ffma2(acc2[1], a.y, p1);
                ffma2(acc2[1], b.x, p2); ffma2(acc2[1], b.y, p3);
                a = w2p[q]; b = w2p[q + 1];
                ffma2(acc2[2], a.x, p0); ffma2(acc2[2], a.y, p1);
                ffma2(acc2[2], b.x, p2); ffma2(acc2[2], b.y, p3);
                a = w3[q]; b = w3[q + 1];
                ffma2(acc2[3], a.x, p0); ffma2(acc2[3], a.y, p1);
                ffma2(acc2[3], b.x, p2); ffma2(acc2[3], b.y, p3);
            }
            __syncthreads();
        }

        // ---- fused epilogue: ReLU -> 1x1 conv (w2) + b2 -> +x -> ReLU
#pragma unroll
        for (int j = 0; j < 4; ++j) {
            float2 e = unpack2(acc2[j]);
            ds[(oc_base + 2 * j + 0) * 33 + lane] = fmaxf(e.x, 0.f);
            ds[(oc_base + 2 * j + 1) * 33 + lane] = fmaxf(e.y, 0.f);
        }
        __syncthreads();

        float eacc[8];
#pragma unroll
        for (int j = 0; j < 8; ++j) eacc[j] = eb[j];

#pragma unroll
        for (int blk = 0; blk < 4; ++blk) {
            float pv[16];
#pragma unroll
            for (int q = 0; q < 16; ++q)
                pv[q] = ds[(blk * 16 + q) * 33 + lane];
#pragma unroll
            for (int j = 0; j < 8; ++j) {
                const float4* wr = (const float4*)(w2 +
                    (oc_base + j) * 64 + blk * 16);
#pragma unroll
                for (int q4 = 0; q4 < 4; ++q4) {
                    float4 w = __ldg(wr + q4);
                    eacc[j] = fmaf(w.x, pv[q4 * 4 + 0], eacc[j]);
                    eacc[j] = fmaf(w.y, pv[q4 * 4 + 1], eacc[j]);
                    eacc[j] = fmaf(w.z, pv[q4 * 4 + 2], eacc[j]);
                    eacc[j] = fmaf(w.w, pv[q4 * 4 + 3], eacc[j]);
                }
            }
        }

        if (pi < n) {
#pragma unroll
            for (int j = 0; j < 8; ++j) {
                int o = oc_base + j;
                out[o * 4096 + mypix] =
                    fmaxf(eacc[j] + __ldg(x + o * 4096 + mypix), 0.f);
            }
        }
        __syncthreads();   // ds (= ps) must drain before next chunk stages
    }
}

// ---------------------------------------------------------------------------
extern "C" void kernel_launch(void* const* d_in, const int* in_sizes, int n_in,
                              void* d_out, int out_size) {
    const float* x       = (const float*)d_in[0];
    const int*   buckets = (const int*)  d_in[1];
    const float* w1      = (const float*)d_in[2];
    const float* b1      = (const float*)d_in[3];
    const float* emb     = (const float*)d_in[4];
    const float* w2      = (const float*)d_in[5];
    const float* b2      = (const float*)d_in[6];
    float* out = (float*)d_out;

    k_gconv<<<64, 256>>>(x, w1, b1);
    k_dyn<<<216, 256>>>(buckets, emb, x, w2, b2, out);
}

// round 11
// speedup vs baseline: 1.3043x; 1.0487x over previous
#include <cuda_runtime.h>

// ---------------------------------------------------------------------------
// EResidualBlockBucket: x -> grouped3x3+ReLU -> per-pixel bucket-indexed
// dynamic 3x3 conv (+per-pixel bias) -> ReLU -> 1x1 conv -> +x -> ReLU
//
// R10 lesson: per-icc weight staging from DRAM is the floor (67-81us across
// 5 variants). R11: load the ENTIRE 147.7KB per-bucket filter with ONE
// cp.async.bulk (TMA) into smem (B200: 227KB/CTA), stage ALL 576-channel
// patches for a 32-pixel chunk once (76KB), then compute with ZERO weight
// restaging and 4 barriers per chunk. Weight rows keep gmem layout; each
// warp owns 4 ocs of equal residue mod 4 so LDS.128 stays 16B-aligned via
// a per-warp c-phase. Pixel lists built by a tiny pre-kernel (smem is full).
// ---------------------------------------------------------------------------

#define HPW 66                 // padded image width/height
#define HPSZ (64 * HPW * HPW)  // h_pad elements: [y][x][ic], ic fastest

__device__ __align__(16) float g_hpad[HPSZ];     // padded h, pixel-major
__device__ int g_cnt[216];                        // pixels per bucket
__device__ unsigned short g_plist[216 * 4096];    // pixel lists (stride 4096)

// dynamic smem layout (bytes)
#define SM_W    0                          // W tile: 64*577*4 = 147712
#define SM_PS   147712                     // patches: 576*33*4 = 76032
#define SM_MBAR 223744                     // mbarrier (8B)
#define SM_TOT  223760

// ---------------- K0: bucket sort (one CTA) --------------------------------
__global__ void __launch_bounds__(1024) k_sort(const int* __restrict__ buckets) {
    __shared__ int cnt[216];
    int tid = threadIdx.x;
    if (tid < 216) cnt[tid] = 0;
    __syncthreads();
    for (int i = tid; i < 4096; i += 1024) {
        int t = buckets[i];
        if ((unsigned)t < 216u) {
            int p = atomicAdd(&cnt[t], 1);
            g_plist[t * 4096 + p] = (unsigned short)i;
        }
    }
    __syncthreads();
    if (tid < 216) g_cnt[tid] = cnt[tid];
}

// ---------------- K1: grouped 3x3 conv + bias + ReLU -> g_hpad -------------
__global__ void __launch_bounds__(256) k_gconv(const float* __restrict__ x,
                                               const float* __restrict__ w1,
                                               const float* __restrict__ b1) {
    __shared__ float xs[16][18][18];
    __shared__ float ws[16][144];
    __shared__ float bs[16];

    int bx = blockIdx.x;
    int g = bx >> 4;
    int tile = bx & 15;
    int y0 = (tile >> 2) * 16, x0 = (tile & 3) * 16;
    int tid = threadIdx.x;

    for (int i = tid; i < 16 * 18 * 18; i += 256) {
        int ic = i / 324;
        int rem = i - ic * 324;
        int r = rem / 18, c = rem - r * 18;
        int yy = y0 - 1 + r, xx = x0 - 1 + c;
        float v = 0.f;
        if (yy >= 0 && yy < 64 && xx >= 0 && xx < 64)
            v = x[(g * 16 + ic) * 4096 + yy * 64 + xx];
        xs[ic][r][c] = v;
    }
    for (int i = tid; i < 16 * 144; i += 256) {
        int oc = i / 144;
        ws[oc][i - oc * 144] = w1[(g * 16 + oc) * 144 + (i - oc * 144)];
    }
    if (tid < 16) bs[tid] = b1[g * 16 + tid];
    __syncthreads();

    int r = tid >> 4, c = tid & 15;
    float acc[16];
#pragma unroll
    for (int j = 0; j < 16; ++j) acc[j] = bs[j];

    for (int ic = 0; ic < 16; ++ic) {
        float p[9];
#pragma unroll
        for (int dy = 0; dy < 3; ++dy)
#pragma unroll
            for (int dx = 0; dx < 3; ++dx)
                p[dy * 3 + dx] = xs[ic][r + dy][c + dx];
#pragma unroll
        for (int j = 0; j < 16; ++j) {
#pragma unroll
            for (int k = 0; k < 9; ++k)
                acc[j] = fmaf(ws[j][ic * 9 + k], p[k], acc[j]);
        }
    }
    float* dst = g_hpad + (((y0 + r + 1) * HPW) + (x0 + c + 1)) * 64 + g * 16;
#pragma unroll
    for (int j = 0; j < 16; ++j) dst[j] = fmaxf(acc[j], 0.f);
}

// ---------------- K2: bucket-grouped dynamic conv + fused epilogue ---------
// grid 216 x 512 threads (16 warps). Warp w owns ocs {oc0 + 16j, j=0..3},
// oc0 = (w&3) + 4*(w>>2): all 4 ocs share residue (w&3) mod 4 so weight
// LDS.128 at 4*(oc*577 + c) is 16B-aligned for c = c0 + 4m, c0 = (-oc)&3.
__global__ void __launch_bounds__(512)
k_dyn(const float* __restrict__ emb, const float* __restrict__ x,
      const float* __restrict__ w2, const float* __restrict__ b2,
      float* __restrict__ out) {
    extern __shared__ __align__(16) char sm[];
    float* wsm = (float*)(sm + SM_W);            // W tile, gmem layout
    float* ps  = (float*)(sm + SM_PS);           // patches [c][slot] pitch 33
    unsigned mbar = (unsigned)__cvta_generic_to_shared(sm + SM_MBAR);

    int t = blockIdx.x;
    int tid = threadIdx.x;
    int n = __ldg(&g_cnt[t]);
    if (n == 0) return;

    int lane = tid & 31;
    int wid = tid >> 5;                          // 0..15
    int r4 = wid & 3;
    int oc0 = r4 + 4 * (wid >> 2);               // ocs oc0 + 16j
    int c0 = (4 - r4) & 3;                       // quad phase
    const float* W = emb + (size_t)t * 36928;
    const unsigned short* plist = g_plist + t * 4096;

    // ---- kick off TMA bulk load of the whole W tile (147712 B) ----
    if (tid == 0) {
        asm volatile("mbarrier.init.shared.b64 [%0], 1;" :: "r"(mbar));
        // make init visible to the async proxy before the bulk op
        asm volatile("fence.proxy.async.shared::cta;" ::: "memory");
        asm volatile("mbarrier.arrive.expect_tx.shared.b64 _, [%0], %1;"
                     :: "r"(mbar), "r"(147712u));
        unsigned wdst = (unsigned)__cvta_generic_to_shared(sm + SM_W);
#pragma unroll
        for (int q = 0; q < 4; ++q) {            // 4 x 36928 B pieces
            asm volatile(
                "cp.async.bulk.shared::cluster.global.mbarrier::complete_tx::bytes"
                " [%0], [%1], %2, [%3];"
                :: "r"(wdst + q * 36928u),
                   "l"((const void*)((const char*)W + q * 36928)),
                   "r"(36928u), "r"(mbar) : "memory");
        }
    }

    // ---- per-thread invariant patch-staging indices ----
    // 4608 float4 items: item i -> q=i&15 (ic quad), r=i>>4, slot=r/9, pos=r%9
    int sq[9], sslot[9], sps[9], sgp[9];
#pragma unroll
    for (int k = 0; k < 9; ++k) {
        int i = tid + 512 * k;
        int q = i & 15;
        int r = i >> 4;
        int slot = r / 9, pos = r - slot * 9;
        int dy = pos / 3, dx = pos - dy * 3;
        sq[k] = q; sslot[k] = slot;
        sps[k] = ((4 * q) * 9 + pos) * 33 + slot;     // + j*9*33 for j
        sgp[k] = (dy * HPW + dx) * 64 + 4 * q;
    }

    // hoisted per-bucket constants
    float bias[4], eb[4];
#pragma unroll
    for (int j = 0; j < 4; ++j) {
        bias[j] = __ldg(W + (oc0 + 16 * j) * 577 + 576);
        eb[j]   = __ldg(b2 + oc0 + 16 * j);
    }

    bool first = true;
    for (int chunk = 0; chunk < n; chunk += 32) {
        int pi = chunk + lane;
        int mypix = __ldg(plist + (pi < n ? pi : n - 1));

        // ---- stage ALL patches for this chunk: 9 float4 items/thread ----
#pragma unroll
        for (int k = 0; k < 9; ++k) {
            int pj = chunk + sslot[k];
            int pix = __ldg(plist + (pj < n ? pj : n - 1));
            const float4 v = *(const float4*)(g_hpad +
                ((pix >> 6) * HPW + (pix & 63)) * 64 + sgp[k]);
            int o = sps[k];
            ps[o +   0] = v.x;     // c = (4q+0)*9+pos
            ps[o + 297] = v.y;     // +9*33
            ps[o + 594] = v.z;
            ps[o + 891] = v.w;
        }
        __syncthreads();

        if (first) {               // wait once for the W TMA
            first = false;
            unsigned done;
            do {
                asm volatile(
                    "{\n\t.reg .pred p;\n\t"
                    "mbarrier.try_wait.parity.acquire.cta.shared::cta.b64 p, [%1], 0, 0x989680;\n\t"
                    "selp.b32 %0, 1, 0, p;\n\t}"
                    : "=r"(done) : "r"(mbar) : "memory");
            } while (!done);
        }

        // ---- compute: 143 aligned c-quads + 4 wrap scalars ----
        float acc[4] = { bias[0], bias[1], bias[2], bias[3] };
        const float* psl = ps + lane;
#pragma unroll 4
        for (int m = 0; m < 143; ++m) {
            int c = c0 + 4 * m;
            float p0 = psl[(c + 0) * 33];
            float p1 = psl[(c + 1) * 33];
            float p2 = psl[(c + 2) * 33];
            float p3 = psl[(c + 3) * 33];
#pragma unroll
            for (int j = 0; j < 4; ++j) {
                const float4 w = *(const float4*)(wsm + (oc0 + 16 * j) * 577 + c);
                acc[j] = fmaf(w.x, p0, acc[j]);
                acc[j] = fmaf(w.y, p1, acc[j]);
                acc[j] = fmaf(w.z, p2, acc[j]);
                acc[j] = fmaf(w.w, p3, acc[j]);
            }
        }
#pragma unroll
        for (int k = 0; k < 4; ++k) {            // leftover c's (wrap)
            int c = c0 + 572 + k;
            if (c >= 576) c -= 576;
            float pe = psl[c * 33];
#pragma unroll
            for (int j = 0; j < 4; ++j)
                acc[j] = fmaf(wsm[(oc0 + 16 * j) * 577 + c], pe, acc[j]);
        }
        __syncthreads();           // ps reads done before ds overlay

        // ---- fused epilogue: ReLU -> 1x1 conv (w2) + b2 -> +x -> ReLU ----
        float* ds = ps;            // 64*33 floats overlay
#pragma unroll
        for (int j = 0; j < 4; ++j)
            ds[(oc0 + 16 * j) * 33 + lane] = fmaxf(acc[j], 0.f);
        __syncthreads();

        float eacc[4] = { eb[0], eb[1], eb[2], eb[3] };
#pragma unroll
        for (int blk = 0; blk < 4; ++blk) {
            float pv[16];
#pragma unroll
            for (int q = 0; q < 16; ++q)
                pv[q] = ds[(blk * 16 + q) * 33 + lane];
#pragma unroll
            for (int j = 0; j < 4; ++j) {
                const float4* wr = (const float4*)(w2 +
                    (oc0 + 16 * j) * 64 + blk * 16);
#pragma unroll
                for (int q4 = 0; q4 < 4; ++q4) {
                    float4 w = __ldg(wr + q4);
                    eacc[j] = fmaf(w.x, pv[q4 * 4 + 0], eacc[j]);
                    eacc[j] = fmaf(w.y, pv[q4 * 4 + 1], eacc[j]);
                    eacc[j] = fmaf(w.z, pv[q4 * 4 + 2], eacc[j]);
                    eacc[j] = fmaf(w.w, pv[q4 * 4 + 3], eacc[j]);
                }
            }
        }

        if (pi < n) {
#pragma unroll
            for (int j = 0; j < 4; ++j) {
                int o = oc0 + 16 * j;
                out[o * 4096 + mypix] =
                    fmaxf(eacc[j] + __ldg(x + o * 4096 + mypix), 0.f);
            }
        }
        __syncthreads();           // ds (= ps) drains before next chunk
    }
}

// ---------------------------------------------------------------------------
extern "C" void kernel_launch(void* const* d_in, const int* in_sizes, int n_in,
                              void* d_out, int out_size) {
    const float* x       = (const float*)d_in[0];
    const int*   buckets = (const int*)  d_in[1];
    const float* w1      = (const float*)d_in[2];
    const float* b1      = (const float*)d_in[3];
    const float* emb     = (const float*)d_in[4];
    const float* w2      = (const float*)d_in[5];
    const float* b2      = (const float*)d_in[6];
    float* out = (float*)d_out;

    cudaFuncSetAttribute(k_dyn, cudaFuncAttributeMaxDynamicSharedMemorySize,
                         SM_TOT);

    k_sort<<<1, 1024>>>(buckets);
    k_gconv<<<64, 256>>>(x, w1, b1);
    k_dyn<<<216, 512, SM_TOT>>>(emb, x, w2, b2, out);
}

// round 12
// speedup vs baseline: 1.3141x; 1.0076x over previous
#include <cuda_runtime.h>

// ---------------------------------------------------------------------------
// EResidualBlockBucket: x -> grouped3x3+ReLU -> per-pixel bucket-indexed
// dynamic 3x3 conv (+per-pixel bias) -> ReLU -> 1x1 conv -> +x -> ReLU
//
// R10 lesson: per-icc weight staging from DRAM is the floor (67-81us across
// 5 variants). R11: load the ENTIRE 147.7KB per-bucket filter with ONE
// cp.async.bulk (TMA) into smem (B200: 227KB/CTA), stage ALL 576-channel
// patches for a 32-pixel chunk once (76KB), then compute with ZERO weight
// restaging and 4 barriers per chunk. Weight rows keep gmem layout; each
// warp owns 4 ocs of equal residue mod 4 so LDS.128 stays 16B-aligned via
// a per-warp c-phase. Pixel lists built by a tiny pre-kernel (smem is full).
// ---------------------------------------------------------------------------

#define HPW 66                 // padded image width/height
#define HPSZ (64 * HPW * HPW)  // h_pad elements: [y][x][ic], ic fastest

__device__ __align__(16) float g_hpad[HPSZ];     // padded h, pixel-major
__device__ int g_cnt[216];                        // pixels per bucket
__device__ unsigned short g_plist[216 * 4096];    // pixel lists (stride 4096)

// dynamic smem layout (bytes)
#define SM_W    0                          // W tile: 64*577*4 = 147712
#define SM_PS   147712                     // patches: 576*33*4 = 76032
#define SM_MBAR 223744                     // mbarrier (8B)
#define SM_TOT  223760

// ---------------- K0: bucket sort (one CTA) --------------------------------
__global__ void __launch_bounds__(1024) k_sort(const int* __restrict__ buckets) {
    __shared__ int cnt[216];
    int tid = threadIdx.x;
    if (tid < 216) cnt[tid] = 0;
    __syncthreads();
    for (int i = tid; i < 4096; i += 1024) {
        int t = buckets[i];
        if ((unsigned)t < 216u) {
            int p = atomicAdd(&cnt[t], 1);
            g_plist[t * 4096 + p] = (unsigned short)i;
        }
    }
    __syncthreads();
    if (tid < 216) g_cnt[tid] = cnt[tid];
}

// ---------------- K1: grouped 3x3 conv + bias + ReLU -> g_hpad -------------
__global__ void __launch_bounds__(256) k_gconv(const float* __restrict__ x,
                                               const float* __restrict__ w1,
                                               const float* __restrict__ b1) {
    __shared__ float xs[16][18][18];
    __shared__ float ws[16][144];
    __shared__ float bs[16];

    int bx = blockIdx.x;
    int g = bx >> 4;
    int tile = bx & 15;
    int y0 = (tile >> 2) * 16, x0 = (tile & 3) * 16;
    int tid = threadIdx.x;

    for (int i = tid; i < 16 * 18 * 18; i += 256) {
        int ic = i / 324;
        int rem = i - ic * 324;
        int r = rem / 18, c = rem - r * 18;
        int yy = y0 - 1 + r, xx = x0 - 1 + c;
        float v = 0.f;
        if (yy >= 0 && yy < 64 && xx >= 0 && xx < 64)
            v = x[(g * 16 + ic) * 4096 + yy * 64 + xx];
        xs[ic][r][c] = v;
    }
    for (int i = tid; i < 16 * 144; i += 256) {
        int oc = i / 144;
        ws[oc][i - oc * 144] = w1[(g * 16 + oc) * 144 + (i - oc * 144)];
    }
    if (tid < 16) bs[tid] = b1[g * 16 + tid];
    __syncthreads();

    int r = tid >> 4, c = tid & 15;
    float acc[16];
#pragma unroll
    for (int j = 0; j < 16; ++j) acc[j] = bs[j];

    for (int ic = 0; ic < 16; ++ic) {
        float p[9];
#pragma unroll
        for (int dy = 0; dy < 3; ++dy)
#pragma unroll
            for (int dx = 0; dx < 3; ++dx)
                p[dy * 3 + dx] = xs[ic][r + dy][c + dx];
#pragma unroll
        for (int j = 0; j < 16; ++j) {
#pragma unroll
            for (int k = 0; k < 9; ++k)
                acc[j] = fmaf(ws[j][ic * 9 + k], p[k], acc[j]);
        }
    }
    float* dst = g_hpad + (((y0 + r + 1) * HPW) + (x0 + c + 1)) * 64 + g * 16;
#pragma unroll
    for (int j = 0; j < 16; ++j) dst[j] = fmaxf(acc[j], 0.f);
}

// ---------------- K2: bucket-grouped dynamic conv + fused epilogue ---------
// grid 216 x 512 threads (16 warps). Warp w owns ocs {oc0 + 16j, j=0..3},
// oc0 = (w&3) + 4*(w>>2): all 4 ocs share residue (w&3) mod 4 so weight
// LDS.128 at 4*(oc*577 + c) is 16B-aligned for c = c0 + 4m, c0 = (-oc)&3.
__global__ void __launch_bounds__(512)
k_dyn(const float* __restrict__ emb, const float* __restrict__ x,
      const float* __restrict__ w2, const float* __restrict__ b2,
      float* __restrict__ out) {
    extern __shared__ __align__(16) char sm[];
    float* wsm = (float*)(sm + SM_W);            // W tile, gmem layout
    float* ps  = (float*)(sm + SM_PS);           // patches [c][slot] pitch 33
    unsigned mbar = (unsigned)__cvta_generic_to_shared(sm + SM_MBAR);

    int t = blockIdx.x;
    int tid = threadIdx.x;
    int n = __ldg(&g_cnt[t]);
    if (n == 0) return;

    int lane = tid & 31;
    int wid = tid >> 5;                          // 0..15
    int r4 = wid & 3;
    int oc0 = r4 + 4 * (wid >> 2);               // ocs oc0 + 16j
    int c0 = (4 - r4) & 3;                       // quad phase
    const float* W = emb + (size_t)t * 36928;
    const unsigned short* plist = g_plist + t * 4096;

    // ---- kick off TMA bulk load of the whole W tile (147712 B) ----
    if (tid == 0) {
        asm volatile("mbarrier.init.shared.b64 [%0], 1;" :: "r"(mbar));
        // make init visible to the async proxy before the bulk op
        asm volatile("fence.proxy.async.shared::cta;" ::: "memory");
        asm volatile("mbarrier.arrive.expect_tx.shared.b64 _, [%0], %1;"
                     :: "r"(mbar), "r"(147712u));
        unsigned wdst = (unsigned)__cvta_generic_to_shared(sm + SM_W);
#pragma unroll
        for (int q = 0; q < 4; ++q) {            // 4 x 36928 B pieces
            asm volatile(
                "cp.async.bulk.shared::cluster.global.mbarrier::complete_tx::bytes"
                " [%0], [%1], %2, [%3];"
                :: "r"(wdst + q * 36928u),
                   "l"((const void*)((const char*)W + q * 36928)),
                   "r"(36928u), "r"(mbar) : "memory");
        }
    }

    // ---- per-thread invariant patch-staging indices ----
    // 4608 float4 items: item i -> q=i&15 (ic quad), r=i>>4, slot=r/9, pos=r%9
    int sq[9], sslot[9], sps[9], sgp[9];
#pragma unroll
    for (int k = 0; k < 9; ++k) {
        int i = tid + 512 * k;
        int q = i & 15;
        int r = i >> 4;
        int slot = r / 9, pos = r - slot * 9;
        int dy = pos / 3, dx = pos - dy * 3;
        sq[k] = q; sslot[k] = slot;
        sps[k] = ((4 * q) * 9 + pos) * 33 + slot;     // + j*9*33 for j
        sgp[k] = (dy * HPW + dx) * 64 + 4 * q;
    }

    // hoisted per-bucket constants
    float bias[4], eb[4];
#pragma unroll
    for (int j = 0; j < 4; ++j) {
        bias[j] = __ldg(W + (oc0 + 16 * j) * 577 + 576);
        eb[j]   = __ldg(b2 + oc0 + 16 * j);
    }

    bool first = true;
    for (int chunk = 0; chunk < n; chunk += 32) {
        int pi = chunk + lane;
        int mypix = __ldg(plist + (pi < n ? pi : n - 1));

        // ---- stage ALL patches for this chunk: 9 float4 items/thread ----
#pragma unroll
        for (int k = 0; k < 9; ++k) {
            int pj = chunk + sslot[k];
            int pix = __ldg(plist + (pj < n ? pj : n - 1));
            const float4 v = *(const float4*)(g_hpad +
                ((pix >> 6) * HPW + (pix & 63)) * 64 + sgp[k]);
            int o = sps[k];
            ps[o +   0] = v.x;     // c = (4q+0)*9+pos
            ps[o + 297] = v.y;     // +9*33
            ps[o + 594] = v.z;
            ps[o + 891] = v.w;
        }
        __syncthreads();

        if (first) {               // wait once for the W TMA
            first = false;
            unsigned done;
            do {
                asm volatile(
                    "{\n\t.reg .pred p;\n\t"
                    "mbarrier.try_wait.parity.acquire.cta.shared::cta.b64 p, [%1], 0, 0x989680;\n\t"
                    "selp.b32 %0, 1, 0, p;\n\t}"
                    : "=r"(done) : "r"(mbar) : "memory");
            } while (!done);
        }

        // ---- compute: 143 aligned c-quads + 4 wrap scalars ----
        float acc[4] = { bias[0], bias[1], bias[2], bias[3] };
        const float* psl = ps + lane;
#pragma unroll 4
        for (int m = 0; m < 143; ++m) {
            int c = c0 + 4 * m;
            float p0 = psl[(c + 0) * 33];
            float p1 = psl[(c + 1) * 33];
            float p2 = psl[(c + 2) * 33];
            float p3 = psl[(c + 3) * 33];
#pragma unroll
            for (int j = 0; j < 4; ++j) {
                const float4 w = *(const float4*)(wsm + (oc0 + 16 * j) * 577 + c);
                acc[j] = fmaf(w.x, p0, acc[j]);
                acc[j] = fmaf(w.y, p1, acc[j]);
                acc[j] = fmaf(w.z, p2, acc[j]);
                acc[j] = fmaf(w.w, p3, acc[j]);
            }
        }
#pragma unroll
        for (int k = 0; k < 4; ++k) {            // leftover c's (wrap)
            int c = c0 + 572 + k;
            if (c >= 576) c -= 576;
            float pe = psl[c * 33];
#pragma unroll
            for (int j = 0; j < 4; ++j)
                acc[j] = fmaf(wsm[(oc0 + 16 * j) * 577 + c], pe, acc[j]);
        }
        __syncthreads();           // ps reads done before ds overlay

        // ---- fused epilogue: ReLU -> 1x1 conv (w2) + b2 -> +x -> ReLU ----
        float* ds = ps;            // 64*33 floats overlay
#pragma unroll
        for (int j = 0; j < 4; ++j)
            ds[(oc0 + 16 * j) * 33 + lane] = fmaxf(acc[j], 0.f);
        __syncthreads();

        float eacc[4] = { eb[0], eb[1], eb[2], eb[3] };
#pragma unroll
        for (int blk = 0; blk < 4; ++blk) {
            float pv[16];
#pragma unroll
            for (int q = 0; q < 16; ++q)
                pv[q] = ds[(blk * 16 + q) * 33 + lane];
#pragma unroll
            for (int j = 0; j < 4; ++j) {
                const float4* wr = (const float4*)(w2 +
                    (oc0 + 16 * j) * 64 + blk * 16);
#pragma unroll
                for (int q4 = 0; q4 < 4; ++q4) {
                    float4 w = __ldg(wr + q4);
                    eacc[j] = fmaf(w.x, pv[q4 * 4 + 0], eacc[j]);
                    eacc[j] = fmaf(w.y, pv[q4 * 4 + 1], eacc[j]);
                    eacc[j] = fmaf(w.z, pv[q4 * 4 + 2], eacc[j]);
                    eacc[j] = fmaf(w.w, pv[q4 * 4 + 3], eacc[j]);
                }
            }
        }

        if (pi < n) {
#pragma unroll
            for (int j = 0; j < 4; ++j) {
                int o = oc0 + 16 * j;
                out[o * 4096 + mypix] =
                    fmaxf(eacc[j] + __ldg(x + o * 4096 + mypix), 0.f);
            }
        }
        __syncthreads();           // ds (= ps) drains before next chunk
    }
}

// ---------------------------------------------------------------------------
extern "C" void kernel_launch(void* const* d_in, const int* in_sizes, int n_in,
                              void* d_out, int out_size) {
    const float* x       = (const float*)d_in[0];
    const int*   buckets = (const int*)  d_in[1];
    const float* w1      = (const float*)d_in[2];
    const float* b1      = (const float*)d_in[3];
    const float* emb     = (const float*)d_in[4];
    const float* w2      = (const float*)d_in[5];
    const float* b2      = (const float*)d_in[6];
    float* out = (float*)d_out;

    cudaFuncSetAttribute(k_dyn, cudaFuncAttributeMaxDynamicSharedMemorySize,
                         SM_TOT);

    k_sort<<<1, 1024>>>(buckets);
    k_gconv<<<64, 256>>>(x, w1, b1);
    k_dyn<<<216, 512, SM_TOT>>>(emb, x, w2, b2, out);
}